// round 2
// baseline (speedup 1.0000x reference)
#include <cuda_runtime.h>

#define BATCH 2048
#define SEQ 128
#define FEAT 64
#define HID 512
#define BM 64
#define BJ 32
#define BK 16
#define NTHREADS 256

// Scratch state (device globals: no allocation allowed). 24 MB total.
__device__ float g_h1a[BATCH * HID];
__device__ float g_h1b[BATCH * HID];
__device__ float g_c1[BATCH * HID];
__device__ float g_c2[BATCH * HID];
__device__ float g_h2a[BATCH * HID];
__device__ float g_h2b[BATCH * HID];

__device__ __forceinline__ float sigmoid_(float v) {
    return 1.0f / (1.0f + __expf(-v));
}

// Fused LSTM step: gates = h_prev@U + x_t@W + bias, then cell update.
// Block computes a [BM x BJ] tile of hidden units (4 gates each => 64x128 GEMM tile).
// Thread (rg, jj): 8 batch rows (rg*8..rg*8+7), 1 hidden unit (jj), all 4 gates.
__global__ __launch_bounds__(NTHREADS) void lstm_step(
    const float* __restrict__ hprev,   // [B, HID] (ignored if first)
    const float* __restrict__ U,       // [HID, 4*HID]
    const float* __restrict__ xt,      // batch row stride = ldx
    int ldx, int Kx,
    const float* __restrict__ W,       // [Kx, 4*HID]
    const float* __restrict__ bias,    // [4*HID]
    float* __restrict__ cstate,        // [B, HID] in-place
    float* __restrict__ hout,          // [B, HID]
    int first)
{
    __shared__ float As[BK][BM + 4];     // pitch 68 floats: float4-aligned rows
    __shared__ float Bs[BK][4 * BJ];     // 16 x 128

    const int m0 = blockIdx.x * BM;
    const int j0 = blockIdx.y * BJ;
    const int tid = threadIdx.x;
    const int jj = tid & 31;
    const int rg = tid >> 5;

    float acc[4][8];
    #pragma unroll
    for (int g = 0; g < 4; ++g) {
        float bv = bias[g * HID + j0 + jj];
        #pragma unroll
        for (int r = 0; r < 8; ++r) acc[g][r] = bv;
    }

    const int n1 = first ? 0 : (HID / BK);   // recurrent part (h0 == 0 -> skip)
    const int n2 = Kx / BK;                  // input part
    const int niter = n1 + n2;

    for (int it = 0; it < niter; ++it) {
        const float* A; int lda; const float* Bm; int k0;
        if (it < n1) { A = hprev; lda = HID; Bm = U; k0 = it * BK; }
        else         { A = xt;    lda = ldx; Bm = W; k0 = (it - n1) * BK; }

        // Load A tile [BM x BK] transposed into As[k][m]
        #pragma unroll
        for (int i = 0; i < (BM * BK) / NTHREADS; ++i) {
            int e = tid + i * NTHREADS;
            int m = e >> 4, k = e & 15;
            As[k][m] = A[(m0 + m) * lda + k0 + k];
        }
        // Load B tile [BK x 128]: gate-column groups {g*HID + j0 + c}
        #pragma unroll
        for (int i = 0; i < (4 * BJ * BK) / NTHREADS; ++i) {
            int e = tid + i * NTHREADS;
            int k = e >> 7, n = e & 127;
            int g = n >> 5, c = n & 31;
            Bs[k][n] = Bm[(k0 + k) * (4 * HID) + g * HID + j0 + c];
        }
        __syncthreads();

        #pragma unroll
        for (int kk = 0; kk < BK; ++kk) {
            const float4* ap = reinterpret_cast<const float4*>(&As[kk][rg * 8]);
            float4 a0 = ap[0], a1 = ap[1];
            float a[8] = {a0.x, a0.y, a0.z, a0.w, a1.x, a1.y, a1.z, a1.w};
            float bv[4];
            #pragma unroll
            for (int g = 0; g < 4; ++g) bv[g] = Bs[kk][g * 32 + jj];
            #pragma unroll
            for (int g = 0; g < 4; ++g)
                #pragma unroll
                for (int r = 0; r < 8; ++r)
                    acc[g][r] = fmaf(a[r], bv[g], acc[g][r]);
        }
        __syncthreads();
    }

    // Fused LSTM cell epilogue (Keras order i,f,c,o; relu cell activation)
    const int j = j0 + jj;
    #pragma unroll
    for (int r = 0; r < 8; ++r) {
        int m = m0 + rg * 8 + r;
        int idx = m * HID + j;
        float iv  = sigmoid_(acc[0][r]);
        float fv  = sigmoid_(acc[1][r]);
        float cin = fmaxf(acc[2][r], 0.0f);
        float ov  = sigmoid_(acc[3][r]);
        float cp  = first ? 0.0f : cstate[idx];
        float cn  = fv * cp + iv * cin;
        cstate[idx] = cn;
        hout[idx]   = ov * fmaxf(cn, 0.0f);
    }
}

// out[b] = h2[b,:] @ Wd + bd  (one warp per batch row)
__global__ __launch_bounds__(256) void dense_kernel(
    const float* __restrict__ h2, const float* __restrict__ Wd,
    const float* __restrict__ bd, float* __restrict__ out)
{
    int b = blockIdx.x * 8 + (threadIdx.x >> 5);
    int lane = threadIdx.x & 31;
    const float* row = h2 + (size_t)b * HID;
    float s = 0.0f;
    #pragma unroll
    for (int k = lane; k < HID; k += 32) s += row[k] * Wd[k];
    #pragma unroll
    for (int o = 16; o > 0; o >>= 1) s += __shfl_xor_sync(0xffffffffu, s, o);
    if (lane == 0) out[b] = s + bd[0];
}

extern "C" void kernel_launch(void* const* d_in, const int* in_sizes, int n_in,
                              void* d_out, int out_size)
{
    const float* x  = (const float*)d_in[0];
    const float* W1 = (const float*)d_in[1];
    const float* U1 = (const float*)d_in[2];
    const float* b1 = (const float*)d_in[3];
    const float* W2 = (const float*)d_in[4];
    const float* U2 = (const float*)d_in[5];
    const float* b2 = (const float*)d_in[6];
    const float* Wd = (const float*)d_in[7];
    const float* bd = (const float*)d_in[8];
    float* out = (float*)d_out;

    float *h1a, *h1b, *c1, *c2, *h2a, *h2b;
    cudaGetSymbolAddress((void**)&h1a, g_h1a);
    cudaGetSymbolAddress((void**)&h1b, g_h1b);
    cudaGetSymbolAddress((void**)&c1, g_c1);
    cudaGetSymbolAddress((void**)&c2, g_c2);
    cudaGetSymbolAddress((void**)&h2a, g_h2a);
    cudaGetSymbolAddress((void**)&h2b, g_h2b);

    float* h1buf[2] = {h1a, h1b};
    float* h2buf[2] = {h2a, h2b};

    dim3 grid(BATCH / BM, HID / BJ);   // 32 x 16 = 512 blocks

    // Interleave layers per timestep: L2(t) consumes h1[t] while it's L2-hot.
    for (int t = 0; t < SEQ; ++t) {
        const float* h1prev = (t == 0) ? nullptr : h1buf[(t - 1) & 1];
        lstm_step<<<grid, NTHREADS>>>(h1prev, U1,
                                      x + (size_t)t * FEAT, SEQ * FEAT, FEAT,
                                      W1, b1, c1, h1buf[t & 1], t == 0);

        const float* h2prev = (t == 0) ? nullptr : h2buf[(t - 1) & 1];
        lstm_step<<<grid, NTHREADS>>>(h2prev, U2,
                                      h1buf[t & 1], HID, HID,
                                      W2, b2, c2, h2buf[t & 1], t == 0);
    }

    dense_kernel<<<BATCH / 8, 256>>>(h2buf[(SEQ - 1) & 1], Wd, bd, out);
}

// round 4
// speedup vs baseline: 2.4572x; 2.4572x over previous
#include <cuda_runtime.h>
#include <cuda_bf16.h>
#include <cstdint>

#define BATCH 2048
#define SEQ   128
#define FEAT  64
#define HID   512
#define NGATE 2048          // 4*HID, gate-interleaved: n = 4*j + g
#define TM    128
#define TN    128
#define TK    32
#define NTH   256

// smem stage layout (pitch-80B rows: 32 bf16 = 64B data + 16B pad, conflict-free ldmatrix)
#define PB       80
#define A_HI     0
#define A_MID    10240
#define B_HI     20480
#define B_MID    30720
#define STAGE    40960
#define BIAS_OFF 81920
#define SMEM_DYN 82432

// ---------------- static device buffers (~105 MB) ----------------
__device__ __nv_bfloat16 g_U1h[NGATE * HID],  g_U1m[NGATE * HID];
__device__ __nv_bfloat16 g_W1h[NGATE * FEAT], g_W1m[NGATE * FEAT];
__device__ __nv_bfloat16 g_U2h[NGATE * HID],  g_U2m[NGATE * HID];
__device__ __nv_bfloat16 g_W2h[NGATE * HID],  g_W2m[NGATE * HID];
__device__ __nv_bfloat16 g_xh[(size_t)BATCH * SEQ * FEAT], g_xm[(size_t)BATCH * SEQ * FEAT];
__device__ __nv_bfloat16 g_h1h[2][BATCH * HID], g_h1m[2][BATCH * HID];
__device__ __nv_bfloat16 g_h2h[2][BATCH * HID], g_h2m[2][BATCH * HID];
__device__ float g_c1[BATCH * HID], g_c2[BATCH * HID];
__device__ float g_b1i[NGATE], g_b2i[NGATE];

// ---------------- PTX helpers (baseline sm_80/90 features only) ----------------
__device__ __forceinline__ uint32_t smem_u32(const void* p) {
    uint32_t a;
    asm("{ .reg .u64 t; cvta.to.shared.u64 t, %1; cvt.u32.u64 %0, t; }" : "=r"(a) : "l"(p));
    return a;
}
__device__ __forceinline__ void cpa(uint32_t dst, const void* src) {
    asm volatile("cp.async.cg.shared.global [%0], [%1], 16;" :: "r"(dst), "l"(src));
}
__device__ __forceinline__ void cp_commit() { asm volatile("cp.async.commit_group;"); }
template <int N> __device__ __forceinline__ void cp_wait() {
    asm volatile("cp.async.wait_group %0;" :: "n"(N));
}
__device__ __forceinline__ void ldm4(uint32_t* r, uint32_t addr) {
    asm volatile("ldmatrix.sync.aligned.m8n8.x4.shared.b16 {%0,%1,%2,%3}, [%4];"
        : "=r"(r[0]), "=r"(r[1]), "=r"(r[2]), "=r"(r[3]) : "r"(addr));
}
__device__ __forceinline__ void mma16816(float* c, const uint32_t* a, const uint32_t* b) {
    asm volatile("mma.sync.aligned.m16n8k16.row.col.f32.bf16.bf16.f32 "
        "{%0,%1,%2,%3}, {%4,%5,%6,%7}, {%8,%9}, {%0,%1,%2,%3};"
        : "+f"(c[0]), "+f"(c[1]), "+f"(c[2]), "+f"(c[3])
        : "r"(a[0]), "r"(a[1]), "r"(a[2]), "r"(a[3]), "r"(b[0]), "r"(b[1]));
}
__device__ __forceinline__ float sigmoid_(float v) { return 1.0f / (1.0f + __expf(-v)); }

// ---------------- fused LSTM step: bf16x3 HMMA GEMM + cell ----------------
__global__ __launch_bounds__(NTH, 2) void lstm_mma(
    const __nv_bfloat16* __restrict__ hph, const __nv_bfloat16* __restrict__ hpm,
    const __nv_bfloat16* __restrict__ Uh,  const __nv_bfloat16* __restrict__ Um, int nRec,
    const __nv_bfloat16* __restrict__ xh,  const __nv_bfloat16* __restrict__ xm, int ldxA,
    const __nv_bfloat16* __restrict__ Wh,  const __nv_bfloat16* __restrict__ Wm, int ldBin, int nIn,
    const float* __restrict__ bint, float* __restrict__ cst,
    __nv_bfloat16* __restrict__ hoh, __nv_bfloat16* __restrict__ hom, int first)
{
    extern __shared__ char smem[];
    const uint32_t sm_base = smem_u32(smem);
    float* biasS = reinterpret_cast<float*>(smem + BIAS_OFF);

    const int tid  = threadIdx.x;
    const int wid  = tid >> 5;
    const int lane = tid & 31;
    const int wm   = wid >> 2;      // 0..1 (M)
    const int wn   = wid & 3;       // 0..3 (N)
    const int m0   = blockIdx.x * TM;
    const int n0   = blockIdx.y * TN;

    if (tid < TN) biasS[tid] = bint[n0 + tid];

    // ldmatrix per-lane row/k mapping (within-stage byte offsets)
    const int rA  = (lane & 7) + ((lane >> 3) & 1) * 8;
    const int kbA = (lane >> 4) * 8;
    const int rB  = (lane & 7) + ((lane >> 4) & 1) * 8;
    const int kbB = ((lane >> 3) & 1) * 8;
    const uint32_t aoff = A_HI + (uint32_t)(wm * 64 + rA) * PB + kbA * 2;
    const uint32_t boff = B_HI + (uint32_t)(wn * 32 + rB) * PB + kbB * 2;

    float acc[4][4][4];
    #pragma unroll
    for (int a = 0; a < 4; ++a)
        #pragma unroll
        for (int b = 0; b < 4; ++b)
            #pragma unroll
            for (int c = 0; c < 4; ++c) acc[a][b][c] = 0.0f;

    const int nb = nRec + nIn;

    auto stage_load = [&](int it, int s) {
        const __nv_bfloat16 *Ah, *Am, *Bh, *Bm; int lda, ldb, k0;
        if (it < nRec) { Ah = hph; Am = hpm; lda = HID;  Bh = Uh; Bm = Um; ldb = HID;   k0 = it * TK; }
        else           { Ah = xh;  Am = xm;  lda = ldxA; Bh = Wh; Bm = Wm; ldb = ldBin; k0 = (it - nRec) * TK; }
        const uint32_t sb = sm_base + (uint32_t)s * STAGE;
        #pragma unroll
        for (int i = 0; i < 2; ++i) {
            int e = tid + i * NTH;
            int row = e >> 2, c = e & 3;
            uint32_t d = (uint32_t)row * PB + c * 16;
            size_t offa = (size_t)(m0 + row) * lda + k0 + c * 8;
            cpa(sb + A_HI  + d, Ah + offa);
            cpa(sb + A_MID + d, Am + offa);
            size_t offb = (size_t)(n0 + row) * ldb + k0 + c * 8;
            cpa(sb + B_HI  + d, Bh + offb);
            cpa(sb + B_MID + d, Bm + offb);
        }
    };

    stage_load(0, 0);
    cp_commit();

    for (int it = 0; it < nb; ++it) {
        if (it + 1 < nb) {
            stage_load(it + 1, (it + 1) & 1);
            cp_commit();
            cp_wait<1>();
        } else {
            cp_wait<0>();
        }
        __syncthreads();

        const uint32_t sb = sm_base + (uint32_t)(it & 1) * STAGE;
        #pragma unroll
        for (int ks = 0; ks < 2; ++ks) {
            uint32_t bh[2][4], bm[2][4];
            #pragma unroll
            for (int p = 0; p < 2; ++p) {
                uint32_t ba = sb + boff + (uint32_t)p * (16 * PB) + ks * 32;
                ldm4(bh[p], ba);
                ldm4(bm[p], ba + (B_MID - B_HI));
            }
            #pragma unroll
            for (int mi = 0; mi < 4; ++mi) {
                uint32_t ah[4], am[4];
                uint32_t aa = sb + aoff + (uint32_t)mi * (16 * PB) + ks * 32;
                ldm4(ah, aa);
                ldm4(am, aa + (A_MID - A_HI));
                #pragma unroll
                for (int ni = 0; ni < 4; ++ni) {
                    const uint32_t* bhp = &bh[ni >> 1][(ni & 1) * 2];
                    const uint32_t* bmp = &bm[ni >> 1][(ni & 1) * 2];
                    mma16816(acc[mi][ni], ah, bhp);
                    mma16816(acc[mi][ni], am, bhp);
                    mma16816(acc[mi][ni], ah, bmp);
                }
            }
        }
        __syncthreads();
    }

    // ---------------- epilogue: bias + gate exchange + fused cell ----------------
    const int jbase = (n0 >> 2) + wn * 8;
    #pragma unroll
    for (int mi = 0; mi < 4; ++mi) {
        #pragma unroll
        for (int ni = 0; ni < 4; ++ni) {
            const int nl = wn * 32 + ni * 8 + (lane & 3) * 2;
            const float bb0 = biasS[nl], bb1 = biasS[nl + 1];
            #pragma unroll
            for (int r = 0; r < 2; ++r) {
                float v0 = acc[mi][ni][r * 2 + 0] + bb0;
                float v1 = acc[mi][ni][r * 2 + 1] + bb1;
                float o0 = __shfl_xor_sync(0xffffffffu, v0, 1);
                float o1 = __shfl_xor_sync(0xffffffffu, v1, 1);
                float gi, gf, gc, go;
                if ((lane & 1) == 0) { gi = v0; gf = v1; gc = o0; go = o1; }
                else                 { gi = o0; gf = o1; gc = v0; go = v1; }
                if ((lane & 1) == 0) {
                    const int m = m0 + wm * 64 + mi * 16 + (lane >> 2) + r * 8;
                    const int j = jbase + ni * 2 + ((lane & 3) >> 1);
                    const size_t idx = (size_t)m * HID + j;
                    float cp = first ? 0.0f : cst[idx];
                    float iv = sigmoid_(gi), fv = sigmoid_(gf);
                    float ci = fmaxf(gc, 0.0f), ov = sigmoid_(go);
                    float cn = fv * cp + iv * ci;
                    cst[idx] = cn;
                    float hv = ov * fmaxf(cn, 0.0f);
                    __nv_bfloat16 hh = __float2bfloat16(hv);
                    hoh[idx] = hh;
                    hom[idx] = __float2bfloat16(hv - __bfloat162float(hh));
                }
            }
        }
    }
}

// ---------------- prep: transpose + split weights [K,4H] -> [n][k] hi/mid ----------------
__global__ void prep_weights(const float* __restrict__ src, __nv_bfloat16* __restrict__ dhi,
                             __nv_bfloat16* __restrict__ dmid, int K)
{
    int idx = blockIdx.x * blockDim.x + threadIdx.x;
    if (idx >= NGATE * K) return;
    int n = idx / K, k = idx - n * K;
    int col = (n & 3) * HID + (n >> 2);          // gate-interleave: n = 4j+g
    float v = src[(size_t)k * NGATE + col];
    __nv_bfloat16 h = __float2bfloat16(v);
    dhi[idx] = h;
    dmid[idx] = __float2bfloat16(v - __bfloat162float(h));
}

__global__ void prep_x(const float* __restrict__ x, __nv_bfloat16* __restrict__ xh,
                       __nv_bfloat16* __restrict__ xm, int n)
{
    int i = blockIdx.x * blockDim.x + threadIdx.x;
    if (i >= n) return;
    float v = x[i];
    __nv_bfloat16 h = __float2bfloat16(v);
    xh[i] = h;
    xm[i] = __float2bfloat16(v - __bfloat162float(h));
}

__global__ void prep_bias(const float* __restrict__ b1, const float* __restrict__ b2,
                          float* __restrict__ d1, float* __restrict__ d2)
{
    int n = blockIdx.x * blockDim.x + threadIdx.x;
    if (n >= NGATE) return;
    int col = (n & 3) * HID + (n >> 2);
    d1[n] = b1[col];
    d2[n] = b2[col];
}

// ---------------- dense head: out[b] = (h2hi+h2mid) @ Wd + bd ----------------
__global__ __launch_bounds__(256) void dense_kernel(
    const __nv_bfloat16* __restrict__ hh, const __nv_bfloat16* __restrict__ hm,
    const float* __restrict__ Wd, const float* __restrict__ bd, float* __restrict__ out)
{
    int b = blockIdx.x * 8 + (threadIdx.x >> 5);
    int lane = threadIdx.x & 31;
    const __nv_bfloat16* rh = hh + (size_t)b * HID;
    const __nv_bfloat16* rm = hm + (size_t)b * HID;
    float s = 0.0f;
    #pragma unroll
    for (int k = lane; k < HID; k += 32)
        s += (__bfloat162float(rh[k]) + __bfloat162float(rm[k])) * Wd[k];
    #pragma unroll
    for (int o = 16; o > 0; o >>= 1) s += __shfl_xor_sync(0xffffffffu, s, o);
    if (lane == 0) out[b] = s + bd[0];
}

extern "C" void kernel_launch(void* const* d_in, const int* in_sizes, int n_in,
                              void* d_out, int out_size)
{
    const float* x  = (const float*)d_in[0];
    const float* W1 = (const float*)d_in[1];
    const float* U1 = (const float*)d_in[2];
    const float* b1 = (const float*)d_in[3];
    const float* W2 = (const float*)d_in[4];
    const float* U2 = (const float*)d_in[5];
    const float* b2 = (const float*)d_in[6];
    const float* Wd = (const float*)d_in[7];
    const float* bd = (const float*)d_in[8];
    float* out = (float*)d_out;

    cudaFuncSetAttribute(lstm_mma, cudaFuncAttributeMaxDynamicSharedMemorySize, SMEM_DYN);

    __nv_bfloat16 *U1h, *U1m, *W1h, *W1m, *U2h, *U2m, *W2h, *W2m, *xh, *xm;
    __nv_bfloat16 *h1h, *h1m, *h2h, *h2m;
    float *c1, *c2, *b1i, *b2i;
    cudaGetSymbolAddress((void**)&U1h, g_U1h); cudaGetSymbolAddress((void**)&U1m, g_U1m);
    cudaGetSymbolAddress((void**)&W1h, g_W1h); cudaGetSymbolAddress((void**)&W1m, g_W1m);
    cudaGetSymbolAddress((void**)&U2h, g_U2h); cudaGetSymbolAddress((void**)&U2m, g_U2m);
    cudaGetSymbolAddress((void**)&W2h, g_W2h); cudaGetSymbolAddress((void**)&W2m, g_W2m);
    cudaGetSymbolAddress((void**)&xh,  g_xh);  cudaGetSymbolAddress((void**)&xm,  g_xm);
    cudaGetSymbolAddress((void**)&h1h, g_h1h); cudaGetSymbolAddress((void**)&h1m, g_h1m);
    cudaGetSymbolAddress((void**)&h2h, g_h2h); cudaGetSymbolAddress((void**)&h2m, g_h2m);
    cudaGetSymbolAddress((void**)&c1,  g_c1);  cudaGetSymbolAddress((void**)&c2,  g_c2);
    cudaGetSymbolAddress((void**)&b1i, g_b1i); cudaGetSymbolAddress((void**)&b2i, g_b2i);

    __nv_bfloat16* h1hb[2] = {h1h, h1h + BATCH * HID};
    __nv_bfloat16* h1mb[2] = {h1m, h1m + BATCH * HID};
    __nv_bfloat16* h2hb[2] = {h2h, h2h + BATCH * HID};
    __nv_bfloat16* h2mb[2] = {h2m, h2m + BATCH * HID};

    prep_weights<<<(NGATE * HID + 255) / 256, 256>>>(U1, U1h, U1m, HID);
    prep_weights<<<(NGATE * FEAT + 255) / 256, 256>>>(W1, W1h, W1m, FEAT);
    prep_weights<<<(NGATE * HID + 255) / 256, 256>>>(U2, U2h, U2m, HID);
    prep_weights<<<(NGATE * HID + 255) / 256, 256>>>(W2, W2h, W2m, HID);
    {
        int nx = BATCH * SEQ * FEAT;
        prep_x<<<(nx + 255) / 256, 256>>>(x, xh, xm, nx);
    }
    prep_bias<<<(NGATE + 255) / 256, 256>>>(b1, b2, b1i, b2i);

    dim3 grid(BATCH / TM, NGATE / TN);   // 16 x 16 = 256 CTAs

    for (int t = 0; t < SEQ; ++t) {
        int pv = (t - 1) & 1, cu = t & 1;
        lstm_mma<<<grid, NTH, SMEM_DYN>>>(
            t ? h1hb[pv] : nullptr, t ? h1mb[pv] : nullptr, U1h, U1m, t ? (HID / TK) : 0,
            xh + (size_t)t * FEAT, xm + (size_t)t * FEAT, SEQ * FEAT,
            W1h, W1m, FEAT, FEAT / TK,
            b1i, c1, h1hb[cu], h1mb[cu], t == 0);
        lstm_mma<<<grid, NTH, SMEM_DYN>>>(
            t ? h2hb[pv] : nullptr, t ? h2mb[pv] : nullptr, U2h, U2m, t ? (HID / TK) : 0,
            h1hb[cu], h1mb[cu], HID,
            W2h, W2m, HID, HID / TK,
            b2i, c2, h2hb[cu], h2mb[cu], t == 0);
    }

    dense_kernel<<<BATCH / 8, 256>>>(h2hb[(SEQ - 1) & 1], h2mb[(SEQ - 1) & 1], Wd, bd, out);
}